// round 16
// baseline (speedup 1.0000x reference)
#include <cuda_runtime.h>
#include <cuda_bf16.h>
#include <math.h>
#include <stdint.h>

#define D      1024
#define A_DIM  64
#define TOPK   32
#define DI     4096
#define BATCH  2
#define SEQ    4096
#define NTOK   (BATCH*SEQ)
#define KPART  4

typedef __nv_bfloat16 bf16;

// ---------------- static scratch ----------------
__device__ float g_x1  [NTOK*(size_t)D];
__device__ float g_bufV[NTOK*(size_t)D];
__device__ float g_bufv[NTOK*(size_t)D];
__device__ float g_bufr[NTOK*(size_t)D];
__device__ float g_q   [NTOK*(size_t)A_DIM];
__device__ float g_k   [NTOK*(size_t)A_DIM];
__device__ float g_pval[NTOK*(size_t)(KPART*TOPK)];
__device__ int   g_pidx[NTOK*(size_t)(KPART*TOPK)];
// bf16 hi/lo activation buffers
__device__ bf16 g_x1h[NTOK*(size_t)D],  g_x1l[NTOK*(size_t)D];
__device__ bf16 g_mAh[NTOK*(size_t)D],  g_mAl[NTOK*(size_t)D];
__device__ bf16 g_mBh[NTOK*(size_t)D],  g_mBl[NTOK*(size_t)D];
__device__ bf16 g_aoh[NTOK*(size_t)D],  g_aol[NTOK*(size_t)D];
__device__ bf16 g_rkh[NTOK*(size_t)D],  g_rkl[NTOK*(size_t)D];
__device__ bf16 g_bgh[NTOK*(size_t)DI], g_bgl[NTOK*(size_t)DI];
// weights hi/lo
#define WSZ ((size_t)14*1024*1024)
__device__ bf16 g_wH[WSZ];
__device__ bf16 g_wL[WSZ];
#define MM ((size_t)1048576)
#define O_TMV ((size_t)0)
#define O_TMR (1*MM)
#define O_SAV (2*MM)
#define O_SAO (3*MM)
#define O_TMO (4*MM)
#define O_CMR (5*MM)
#define O_CMK (6*MM)
#define O_CMV (10*MM)

__device__ __forceinline__ float sigmoidf_(float x) { return 1.f/(1.f+expf(-x)); }
__device__ __forceinline__ uint32_t pack_bf2(bf16 a, bf16 b) {
    return (uint32_t)__bfloat16_as_ushort(a) | ((uint32_t)__bfloat16_as_ushort(b) << 16);
}
__device__ __forceinline__ void split_bf(float x, bf16& h, bf16& l) {
    h = __float2bfloat16_rn(x);
    l = __float2bfloat16_rn(x - __bfloat162float(h));
}
__device__ __forceinline__ uint32_t smem_u32(const void* p) {
    uint32_t a;
    asm("{ .reg .u64 t; cvta.to.shared.u64 t, %1; cvt.u32.u64 %0, t; }" : "=r"(a) : "l"(p));
    return a;
}
__device__ __forceinline__ void cp_async16(uint32_t dst, const void* src) {
    asm volatile("cp.async.cg.shared.global [%0], [%1], 16;" :: "r"(dst), "l"(src));
}

// ---------------- fp32 -> bf16 hi/lo split (device body) ----------------
__device__ __forceinline__ void split_body(
    const float* __restrict__ in, bf16* __restrict__ h, bf16* __restrict__ l, int blk)
{
    size_t i = (size_t)blk * 256 + threadIdx.x;
    float4 v = ((const float4*)in)[i];
    bf16 h0,h1,h2,h3,l0,l1,l2,l3;
    split_bf(v.x,h0,l0); split_bf(v.y,h1,l1); split_bf(v.z,h2,l2); split_bf(v.w,h3,l3);
    ((uint2*)h)[i] = make_uint2(pack_bf2(h0,h1), pack_bf2(h2,h3));
    ((uint2*)l)[i] = make_uint2(pack_bf2(l0,l1), pack_bf2(l2,l3));
}

// ---------------- rmsnorm + mixes body ----------------
__device__ __forceinline__ void norm_body(
    int t,
    const float* __restrict__ x, const float* __restrict__ w,
    const float* __restrict__ mA, const float* __restrict__ mB,
    float* __restrict__ oN, bf16* __restrict__ oNh, bf16* __restrict__ oNl,
    bf16* __restrict__ oAh, bf16* __restrict__ oAl,
    bf16* __restrict__ oBh, bf16* __restrict__ oBl)
{
    int tp = ((t % SEQ) == 0) ? t : t - 1;
    int i  = threadIdx.x;
    const float4* xc4 = (const float4*)(x + (size_t)t  * D);
    const float4* xp4 = (const float4*)(x + (size_t)tp * D);
    float4 vc = xc4[i];
    float4 vp = xp4[i];
    float sc = vc.x*vc.x + vc.y*vc.y + vc.z*vc.z + vc.w*vc.w;
    float sp = vp.x*vp.x + vp.y*vp.y + vp.z*vp.z + vp.w*vp.w;
    #pragma unroll
    for (int o = 16; o > 0; o >>= 1) {
        sc += __shfl_xor_sync(0xffffffffu, sc, o);
        sp += __shfl_xor_sync(0xffffffffu, sp, o);
    }
    __shared__ float rc[8], rp[8];
    int wd = i >> 5, lane = i & 31;
    if (lane == 0) { rc[wd] = sc; rp[wd] = sp; }
    __syncthreads();
    sc = 0.f; sp = 0.f;
    #pragma unroll
    for (int j = 0; j < 8; j++) { sc += rc[j]; sp += rp[j]; }
    float invc = 1.f / (sqrtf(sc * (1.f / D)) + 1e-8f);
    float invp = 1.f / (sqrtf(sp * (1.f / D)) + 1e-8f);

    float4 w4 = ((const float4*)w)[i];
    float4 a4 = ((const float4*)mA)[i];
    float4 b4 = ((const float4*)mB)[i];
    float4 n, xs, ra, rb;
    n.x = w4.x*vc.x*invc;  n.y = w4.y*vc.y*invc;  n.z = w4.z*vc.z*invc;  n.w = w4.w*vc.w*invc;
    xs.x = w4.x*vp.x*invp; xs.y = w4.y*vp.y*invp; xs.z = w4.z*vp.z*invp; xs.w = w4.w*vp.w*invp;
    ra.x = n.x*a4.x + xs.x*(1.f-a4.x); ra.y = n.y*a4.y + xs.y*(1.f-a4.y);
    ra.z = n.z*a4.z + xs.z*(1.f-a4.z); ra.w = n.w*a4.w + xs.w*(1.f-a4.w);
    rb.x = n.x*b4.x + xs.x*(1.f-b4.x); rb.y = n.y*b4.y + xs.y*(1.f-b4.y);
    rb.z = n.z*b4.z + xs.z*(1.f-b4.z); rb.w = n.w*b4.w + xs.w*(1.f-b4.w);

    size_t base = (size_t)t * D;
    if (oN) ((float4*)(oN + base))[i] = n;
    bf16 h0,h1,h2,h3,l0,l1,l2,l3;
    if (oNh) {
        split_bf(n.x,h0,l0); split_bf(n.y,h1,l1); split_bf(n.z,h2,l2); split_bf(n.w,h3,l3);
        ((uint2*)(oNh + base))[i] = make_uint2(pack_bf2(h0,h1), pack_bf2(h2,h3));
        ((uint2*)(oNl + base))[i] = make_uint2(pack_bf2(l0,l1), pack_bf2(l2,l3));
    }
    split_bf(ra.x,h0,l0); split_bf(ra.y,h1,l1); split_bf(ra.z,h2,l2); split_bf(ra.w,h3,l3);
    ((uint2*)(oAh + base))[i] = make_uint2(pack_bf2(h0,h1), pack_bf2(h2,h3));
    ((uint2*)(oAl + base))[i] = make_uint2(pack_bf2(l0,l1), pack_bf2(l2,l3));
    split_bf(rb.x,h0,l0); split_bf(rb.y,h1,l1); split_bf(rb.z,h2,l2); split_bf(rb.w,h3,l3);
    ((uint2*)(oBh + base))[i] = make_uint2(pack_bf2(h0,h1), pack_bf2(h2,h3));
    ((uint2*)(oBl + base))[i] = make_uint2(pack_bf2(l0,l1), pack_bf2(l2,l3));
}

__global__ void __launch_bounds__(256) norm_mix_kernel(
    const float* __restrict__ x, const float* __restrict__ w,
    const float* __restrict__ mA, const float* __restrict__ mB,
    float* __restrict__ oN, bf16* __restrict__ oNh, bf16* __restrict__ oNl,
    bf16* __restrict__ oAh, bf16* __restrict__ oAl,
    bf16* __restrict__ oBh, bf16* __restrict__ oBl)
{
    norm_body(blockIdx.x, x, w, mA, mB, oN, oNh, oNl, oAh, oAl, oBh, oBl);
}

// fat norm1: [0,NTOK) norm | then 3 weight splits (tmv,tmr,sav)
struct Norm1Args {
    const float *x, *w, *mA, *mB;
    float *oN; bf16 *oNh, *oNl, *oAh, *oAl, *oBh, *oBl;
    const float *tmv_w, *tmr_w, *sav_w;
    bf16 *wH, *wL;
};
__global__ void __launch_bounds__(256) k_norm1fat(Norm1Args a)
{
    int idx = blockIdx.x;
    if (idx < NTOK) {
        norm_body(idx, a.x, a.w, a.mA, a.mB, a.oN, a.oNh, a.oNl, a.oAh, a.oAl, a.oBh, a.oBl);
    } else if (idx < NTOK + 1024) {
        split_body(a.tmv_w, a.wH + O_TMV, a.wL + O_TMV, idx - NTOK);
    } else if (idx < NTOK + 2048) {
        split_body(a.tmr_w, a.wH + O_TMR, a.wL + O_TMR, idx - NTOK - 1024);
    } else {
        split_body(a.sav_w, a.wH + O_SAV, a.wL + O_SAV, idx - NTOK - 2048);
    }
}

// ---------------- BK=32 double-buffered cp.async mma.sync bf16x3 GEMM tile ----------------
#define MMA_BF16(d, a, b) \
    asm volatile("mma.sync.aligned.m16n8k16.row.col.f32.bf16.bf16.f32 " \
        "{%0,%1,%2,%3}, {%4,%5,%6,%7}, {%8,%9}, {%0,%1,%2,%3};" \
        : "+f"((d)[0]), "+f"((d)[1]), "+f"((d)[2]), "+f"((d)[3]) \
        : "r"((a)[0]), "r"((a)[1]), "r"((a)[2]), "r"((a)[3]), \
          "r"((b)[0]), "r"((b)[1]))
#define LDSM_X4(r0,r1,r2,r3,addr) \
    asm volatile("ldmatrix.sync.aligned.m8n8.x4.shared.b16 {%0,%1,%2,%3}, [%4];" \
        : "=r"(r0),"=r"(r1),"=r"(r2),"=r"(r3) : "r"(addr))

#define RB2     80
#define TILE2   (128*RB2)          // 10240 B
#define STAGE2  (4*TILE2)          // 40960 B
#define GEMM_SMEM (2*STAGE2)       // 81920 B

// mode: 0 plain, 1 +bias, 2 relu^2, 3 sig(P1)*(acc+bias+P2), 4 P1+acc, 5 P1+sig(P2)*acc
template<int WF32, int WBF>
__device__ __forceinline__ void gemm_tile(
    int mode, int bx, int by, char* sm,
    const bf16* __restrict__ Ah, const bf16* __restrict__ Al,
    const bf16* __restrict__ Wh, const bf16* __restrict__ Wl,
    float* __restrict__ Cmat, bf16* __restrict__ Ch, bf16* __restrict__ Cl,
    int Din, int Dout, const float* __restrict__ bias,
    const float* __restrict__ P1, const float* __restrict__ P2)
{
    const int tid  = threadIdx.x;
    const int lane = tid & 31, wid = tid >> 5;
    const int g    = lane >> 2, t4 = lane & 3;
    const int wm   = wid & 1, wn = wid >> 1;
    const int m0   = by * 128, n0 = bx * 128;
    const uint32_t sb = smem_u32(sm);

    const int r0_ = tid >> 2, q0_ = tid & 3;
    const int r1_ = (tid + 256) >> 2, q1_ = q0_;
    const size_t offA0 = (size_t)(m0 + r0_) * Din + q0_ * 8;
    const size_t offA1 = (size_t)(m0 + r1_) * Din + q1_ * 8;
    const size_t offB0 = (size_t)(n0 + r0_) * Din + q0_ * 8;
    const size_t offB1 = (size_t)(n0 + r1_) * Din + q1_ * 8;
    const uint32_t sd0 = (uint32_t)(r0_ * RB2 + q0_ * 16);
    const uint32_t sd1 = (uint32_t)(r1_ * RB2 + q1_ * 16);

    const uint32_t a_lane = (uint32_t)((lane & 15) * RB2 + (lane >> 4) * 16);
    const uint32_t b_lane = (uint32_t)((((lane >> 4) & 1) * 8 + (lane & 7)) * RB2 + ((lane >> 3) & 1) * 16);

    float acc[4][4][4] = {};
    const int nck = Din >> 5;

    {
        uint32_t d = sb;
        cp_async16(d + 0*TILE2 + sd0, Ah + offA0);  cp_async16(d + 0*TILE2 + sd1, Ah + offA1);
        cp_async16(d + 1*TILE2 + sd0, Al + offA0);  cp_async16(d + 1*TILE2 + sd1, Al + offA1);
        cp_async16(d + 2*TILE2 + sd0, Wh + offB0);  cp_async16(d + 2*TILE2 + sd1, Wh + offB1);
        cp_async16(d + 3*TILE2 + sd0, Wl + offB0);  cp_async16(d + 3*TILE2 + sd1, Wl + offB1);
        asm volatile("cp.async.commit_group;");
    }

    for (int c = 0; c < nck; c++) {
        if (c + 1 < nck) {
            size_t k = (size_t)(c + 1) << 5;
            uint32_t d = sb + ((c + 1) & 1) * STAGE2;
            cp_async16(d + 0*TILE2 + sd0, Ah + offA0 + k);  cp_async16(d + 0*TILE2 + sd1, Ah + offA1 + k);
            cp_async16(d + 1*TILE2 + sd0, Al + offA0 + k);  cp_async16(d + 1*TILE2 + sd1, Al + offA1 + k);
            cp_async16(d + 2*TILE2 + sd0, Wh + offB0 + k);  cp_async16(d + 2*TILE2 + sd1, Wh + offB1 + k);
            cp_async16(d + 3*TILE2 + sd0, Wl + offB0 + k);  cp_async16(d + 3*TILE2 + sd1, Wl + offB1 + k);
        }
        asm volatile("cp.async.commit_group;");
        asm volatile("cp.async.wait_group 1;");
        __syncthreads();

        const uint32_t st = sb + (uint32_t)(c & 1) * STAGE2;
        #pragma unroll
        for (int kh = 0; kh < 2; kh++) {
            const uint32_t koff = (uint32_t)(kh * 32);
            uint32_t bh[4][2], bl[4][2];
            {
                uint32_t r0,r1,r2,r3;
                LDSM_X4(r0,r1,r2,r3, st + 2*TILE2 + (uint32_t)((wn*32+ 0)*RB2) + koff + b_lane);
                bh[0][0]=r0; bh[0][1]=r1; bh[1][0]=r2; bh[1][1]=r3;
                LDSM_X4(r0,r1,r2,r3, st + 2*TILE2 + (uint32_t)((wn*32+16)*RB2) + koff + b_lane);
                bh[2][0]=r0; bh[2][1]=r1; bh[3][0]=r2; bh[3][1]=r3;
                LDSM_X4(r0,r1,r2,r3, st + 3*TILE2 + (uint32_t)((wn*32+ 0)*RB2) + koff + b_lane);
                bl[0][0]=r0; bl[0][1]=r1; bl[1][0]=r2; bl[1][1]=r3;
                LDSM_X4(r0,r1,r2,r3, st + 3*TILE2 + (uint32_t)((wn*32+16)*RB2) + koff + b_lane);
                bl[2][0]=r0; bl[2][1]=r1; bl[3][0]=r2; bl[3][1]=r3;
            }
            // term-blocked MMA order: consecutive MMAs hit different accumulators
            // (chain distance per acc goes 1 -> 4); per-acc arithmetic order unchanged.
            #pragma unroll
            for (int tm = 0; tm < 4; tm++) {
                uint32_t ah[4], al[4];
                LDSM_X4(ah[0],ah[1],ah[2],ah[3], st + 0*TILE2 + (uint32_t)((wm*64+tm*16)*RB2) + koff + a_lane);
                LDSM_X4(al[0],al[1],al[2],al[3], st + 1*TILE2 + (uint32_t)((wm*64+tm*16)*RB2) + koff + a_lane);
                #pragma unroll
                for (int tn = 0; tn < 4; tn++) MMA_BF16(acc[tm][tn], ah, bh[tn]);
                #pragma unroll
                for (int tn = 0; tn < 4; tn++) MMA_BF16(acc[tm][tn], al, bh[tn]);
                #pragma unroll
                for (int tn = 0; tn < 4; tn++) MMA_BF16(acc[tm][tn], ah, bl[tn]);
            }
        }
        __syncthreads();
    }

    #pragma unroll
    for (int tm = 0; tm < 4; tm++) {
        int r0 = m0 + wm*64 + tm*16 + g;
        #pragma unroll
        for (int tn = 0; tn < 4; tn++) {
            int cn = n0 + wn*32 + tn*8 + 2*t4;
            size_t i0 = (size_t)r0 * Dout + cn;
            size_t i1 = i0 + (size_t)8 * Dout;
            float v00 = acc[tm][tn][0], v01 = acc[tm][tn][1];
            float v10 = acc[tm][tn][2], v11 = acc[tm][tn][3];
            if (mode == 1) {
                float2 bb = *(const float2*)(bias + cn);
                v00 += bb.x; v01 += bb.y; v10 += bb.x; v11 += bb.y;
            } else if (mode == 2) {
                v00 = fmaxf(v00,0.f); v00 *= v00;  v01 = fmaxf(v01,0.f); v01 *= v01;
                v10 = fmaxf(v10,0.f); v10 *= v10;  v11 = fmaxf(v11,0.f); v11 *= v11;
            } else if (mode == 3) {
                float2 bb = *(const float2*)(bias + cn);
                float2 p10 = *(const float2*)(P1 + i0), p11 = *(const float2*)(P1 + i1);
                float2 p20 = *(const float2*)(P2 + i0), p21 = *(const float2*)(P2 + i1);
                v00 = sigmoidf_(p10.x) * (v00 + bb.x + p20.x);
                v01 = sigmoidf_(p10.y) * (v01 + bb.y + p20.y);
                v10 = sigmoidf_(p11.x) * (v10 + bb.x + p21.x);
                v11 = sigmoidf_(p11.y) * (v11 + bb.y + p21.y);
            } else if (mode == 4) {
                float2 p10 = *(const float2*)(P1 + i0), p11 = *(const float2*)(P1 + i1);
                v00 += p10.x; v01 += p10.y; v10 += p11.x; v11 += p11.y;
            } else if (mode == 5) {
                float2 p10 = *(const float2*)(P1 + i0), p11 = *(const float2*)(P1 + i1);
                float2 p20 = *(const float2*)(P2 + i0), p21 = *(const float2*)(P2 + i1);
                v00 = p10.x + sigmoidf_(p20.x) * v00;
                v01 = p10.y + sigmoidf_(p20.y) * v01;
                v10 = p11.x + sigmoidf_(p21.x) * v10;
                v11 = p11.y + sigmoidf_(p21.y) * v11;
            }
            if (WF32) {
                *(float2*)(Cmat + i0) = make_float2(v00, v01);
                *(float2*)(Cmat + i1) = make_float2(v10, v11);
            }
            if (WBF) {
                bf16 h0,h1,l0,l1;
                split_bf(v00,h0,l0); split_bf(v01,h1,l1);
                *(uint32_t*)(Ch + i0) = pack_bf2(h0,h1);
                *(uint32_t*)(Cl + i0) = pack_bf2(l0,l1);
                split_bf(v10,h0,l0); split_bf(v11,h1,l1);
                *(uint32_t*)(Ch + i1) = pack_bf2(h0,h1);
                *(uint32_t*)(Cl + i1) = pack_bf2(l0,l1);
            }
        }
    }
}

// standalone GEMM wrapper
template<int WF32, int WBF>
__global__ void __launch_bounds__(256, 2) k_gemm(
    int mode,
    const bf16* __restrict__ Ah, const bf16* __restrict__ Al,
    const bf16* __restrict__ Wh, const bf16* __restrict__ Wl,
    float* __restrict__ Cmat, bf16* __restrict__ Ch, bf16* __restrict__ Cl,
    int Din, int Dout, const float* __restrict__ bias,
    const float* __restrict__ P1, const float* __restrict__ P2)
{
    extern __shared__ __align__(16) char sm[];
    gemm_tile<WF32,WBF>(mode, blockIdx.x, blockIdx.y, sm,
                        Ah, Al, Wh, Wl, Cmat, Ch, Cl, Din, Dout, bias, P1, P2);
}

// fat1: [0,512) tmv | [512,1024) tmr | [1024,1536) sav | then 5 weight splits
struct Fat1Args {
    const bf16 *mAh, *mAl, *mBh, *mBl, *x1h, *x1l;
    bf16 *wH, *wL;
    float *bufv, *bufr, *bufV;
    const float *sa_v_b;
    const float *sa_o_w, *tm_out_w, *cm_recept_w, *cm_key_w, *cm_value_w;
};
__global__ void __launch_bounds__(256, 2) k_fat1(Fat1Args a)
{
    extern __shared__ __align__(16) char sm[];
    int idx = blockIdx.x;
    if (idx < 512) {
        gemm_tile<1,0>(0, idx & 7, idx >> 3, sm, a.mAh, a.mAl, a.wH+O_TMV, a.wL+O_TMV,
                       a.bufv, nullptr, nullptr, D, D, nullptr, nullptr, nullptr);
    } else if (idx < 1024) {
        idx -= 512;
        gemm_tile<1,0>(0, idx & 7, idx >> 3, sm, a.mBh, a.mBl, a.wH+O_TMR, a.wL+O_TMR,
                       a.bufr, nullptr, nullptr, D, D, nullptr, nullptr, nullptr);
    } else if (idx < 1536) {
        idx -= 1024;
        gemm_tile<1,0>(1, idx & 7, idx >> 3, sm, a.x1h, a.x1l, a.wH+O_SAV, a.wL+O_SAV,
                       a.bufV, nullptr, nullptr, D, D, a.sa_v_b, nullptr, nullptr);
    } else if (idx < 2560) {
        split_body(a.sa_o_w,      a.wH + O_SAO, a.wL + O_SAO, idx - 1536);
    } else if (idx < 3584) {
        split_body(a.tm_out_w,    a.wH + O_TMO, a.wL + O_TMO, idx - 2560);
    } else if (idx < 4608) {
        split_body(a.cm_recept_w, a.wH + O_CMR, a.wL + O_CMR, idx - 3584);
    } else if (idx < 8704) {
        split_body(a.cm_key_w,    a.wH + O_CMK, a.wL + O_CMK, idx - 4608);
    } else {
        split_body(a.cm_value_w,  a.wH + O_CMV, a.wL + O_CMV, idx - 8704);
    }
}

// fat2: [0,2048) cmk (Dout=DI, relu^2 -> bf16) | [2048,2560) cmr (plain f32)
struct Fat2Args {
    const bf16 *mAh, *mAl, *mBh, *mBl;
    bf16 *wH, *wL, *bgh, *bgl;
    float *bufV;
};
__global__ void __launch_bounds__(256, 2) k_fat2(Fat2Args a)
{
    extern __shared__ __align__(16) char sm[];
    int idx = blockIdx.x;
    if (idx < 2048) {
        gemm_tile<0,1>(2, idx & 31, idx >> 5, sm, a.mAh, a.mAl, a.wH+O_CMK, a.wL+O_CMK,
                       nullptr, a.bgh, a.bgl, D, DI, nullptr, nullptr, nullptr);
    } else {
        idx -= 2048;
        gemm_tile<1,0>(0, idx & 7, idx >> 3, sm, a.mBh, a.mBl, a.wH+O_CMR, a.wL+O_CMR,
                       a.bufV, nullptr, nullptr, D, D, nullptr, nullptr, nullptr);
    }
}

// ---------------- Q+K projections, batched over z ----------------
__global__ void __launch_bounds__(256) qk_gemm(
    const float* __restrict__ Amat,
    const float* __restrict__ qw, const float* __restrict__ qbias, float* __restrict__ qout,
    const float* __restrict__ kw, const float* __restrict__ kbias, float* __restrict__ kout)
{
    const float* Wmat = blockIdx.z ? kw : qw;
    const float* bias = blockIdx.z ? kbias : qbias;
    float* Cmat       = blockIdx.z ? kout : qout;
    const int Din = D, Dout = A_DIM;
    const int BM = 32, BN = 64, BK = 32, TN = 4;
    __shared__ float As[32][32];
    __shared__ float Bs[32][64];
    const int m0 = blockIdx.y * BM;
    const int tid = threadIdx.x;
    const int row = tid / (BN/TN);
    const int col = tid % (BN/TN);
    float acc[2][4] = {};

    for (int k0 = 0; k0 < Din; k0 += BK) {
        {
            int m  = tid / (BK/4);
            int kq = tid % (BK/4);
            float4 v = *(const float4*)(Amat + (size_t)(m0+m)*Din + k0 + kq*4);
            As[kq*4+0][m] = v.x; As[kq*4+1][m] = v.y;
            As[kq*4+2][m] = v.z; As[kq*4+3][m] = v.w;
        }
        #pragma unroll
        for (int l = 0; l < 2; l++) {
            int idx = tid + l*256;
            int n  = idx / (BK/4);
            int kq = idx % (BK/4);
            float4 v = *(const float4*)(Wmat + (size_t)n*Din + k0 + kq*4);
            Bs[kq*4+0][n] = v.x; Bs[kq*4+1][n] = v.y;
            Bs[kq*4+2][n] = v.z; Bs[kq*4+3][n] = v.w;
        }
        __syncthreads();
        #pragma unroll
        for (int k = 0; k < BK; k++) {
            float a0 = As[k][row*2], a1 = As[k][row*2+1];
            #pragma unroll
            for (int j = 0; j < 4; j++) {
                float b = Bs[k][col*4 + j];
                acc[0][j] += a0 * b;
                acc[1][j] += a1 * b;
            }
        }
        __syncthreads();
    }
    #pragma unroll
    for (int i = 0; i < 2; i++) {
        int m = m0 + row*2 + i;
        #pragma unroll
        for (int j = 0; j < 4; j++) {
            int n = col*4 + j;
            Cmat[(size_t)m * Dout + n] = acc[i][j] + bias[n];
        }
    }
}

// ---------------- top-k stage 1: per-partition top-32 ----------------
__global__ void __launch_bounds__(64) topk_part(
    const float* __restrict__ Q, const float* __restrict__ K,
    float* __restrict__ pval, int* __restrict__ pidx)
{
    int q = blockIdx.x * 64 + threadIdx.x;
    int part = blockIdx.y;
    int b = q / SEQ;
    int kbase = part * (SEQ / KPART);
    __shared__ float4 ks[128 * 16];

    float qr[A_DIM];
    const float4* q4 = (const float4*)(Q + (size_t)q * A_DIM);
    #pragma unroll
    for (int i = 0; i < 16; i++) {
        float4 t = q4[i];
        qr[4*i] = t.x; qr[4*i+1] = t.y; qr[4*i+2] = t.z; qr[4*i+3] = t.w;
    }

    float hv[TOPK]; int hi[TOPK];
    #pragma unroll
    for (int i = 0; i < TOPK; i++) { hv[i] = -3.0e38f; hi[i] = 0; }

    for (int kt = 0; kt < SEQ/KPART; kt += 128) {
        __syncthreads();
        const float4* kg = (const float4*)(K + ((size_t)b*SEQ + kbase + kt) * A_DIM);
        for (int l = threadIdx.x; l < 128*16; l += 64) ks[l] = kg[l];
        __syncthreads();
        for (int kk = 0; kk < 128; kk++) {
            float s0 = 0.f, s1 = 0.f, s2 = 0.f, s3 = 0.f;
            #pragma unroll
            for (int a = 0; a < 16; a++) {
                float4 kv = ks[kk*16 + a];
                s0 += qr[4*a]   * kv.x;
                s1 += qr[4*a+1] * kv.y;
                s2 += qr[4*a+2] * kv.z;
                s3 += qr[4*a+3] * kv.w;
            }
            float s = ((s0 + s1) + (s2 + s3)) * 0.125f;
            if (s > hv[0]) {
                int key = kbase + kt + kk;
                int p = 0;
                while (true) {
                    int c1 = 2*p + 1, c2 = 2*p + 2;
                    if (c1 >= TOPK) break;
                    int c = c1;
                    if (c2 < TOPK && hv[c2] < hv[c1]) c = c2;
                    if (hv[c] >= s) break;
                    hv[p] = hv[c]; hi[p] = hi[c]; p = c;
                }
                hv[p] = s; hi[p] = key;
            }
        }
    }
    size_t base = ((size_t)q * KPART + part) * TOPK;
    #pragma unroll
    for (int i = 0; i < TOPK; i++) { pval[base + i] = hv[i]; pidx[base + i] = hi[i]; }
}

// ---------------- fused top-k merge + softmax + gather ----------------
__global__ void __launch_bounds__(256) topk_mg(
    const float* __restrict__ pval, const int* __restrict__ pidx,
    const float* __restrict__ V, bf16* __restrict__ Oh, bf16* __restrict__ Ol)
{
    int q = blockIdx.x;
    int b = q / SEQ;
    __shared__ float sw[TOPK];
    __shared__ int   si[TOPK];
    if (threadIdx.x == 0) {
        float hv[TOPK]; int hi[TOPK];
        #pragma unroll
        for (int i = 0; i < TOPK; i++) { hv[i] = -3.0e38f; hi[i] = 0; }
        size_t base = (size_t)q * (KPART*TOPK);
        for (int j = 0; j < KPART*TOPK; j++) {
            float s = pval[base + j];
            if (s > hv[0]) {
                int key = pidx[base + j];
                int p = 0;
                while (true) {
                    int c1 = 2*p + 1, c2 = 2*p + 2;
                    if (c1 >= TOPK) break;
                    int c = c1;
                    if (c2 < TOPK && hv[c2] < hv[c1]) c = c2;
                    if (hv[c] >= s) break;
                    hv[p] = hv[c]; hi[p] = hi[c]; p = c;
                }
                hv[p] = s; hi[p] = key;
            }
        }
        float m = -3.0e38f;
        #pragma unroll
        for (int i = 0; i < TOPK; i++) m = fmaxf(m, hv[i]);
        float e[TOPK]; float sum = 0.f;
        #pragma unroll
        for (int i = 0; i < TOPK; i++) { e[i] = expf(hv[i] - m); sum += e[i]; }
        float inv = 1.f / sum;
        #pragma unroll
        for (int i = 0; i < TOPK; i++) { sw[i] = e[i] * inv; si[i] = hi[i]; }
    }
    __syncthreads();
    int c = threadIdx.x;
    float4 acc = {0.f, 0.f, 0.f, 0.f};
    #pragma unroll 8
    for (int j = 0; j < TOPK; j++) {
        float w = sw[j];
        const float4* vr = (const float4*)(V + ((size_t)b*SEQ + si[j]) * D);
        float4 vv = vr[c];
        acc.x += w*vv.x; acc.y += w*vv.y; acc.z += w*vv.z; acc.w += w*vv.w;
    }
    bf16 h0,h1,h2,h3,l0,l1,l2,l3;
    split_bf(acc.x,h0,l0); split_bf(acc.y,h1,l1); split_bf(acc.z,h2,l2); split_bf(acc.w,h3,l3);
    size_t base = (size_t)q * D;
    ((uint2*)(Oh + base))[c] = make_uint2(pack_bf2(h0,h1), pack_bf2(h2,h3));
    ((uint2*)(Ol + base))[c] = make_uint2(pack_bf2(l0,l1), pack_bf2(l2,l3));
}

// ---------------- launch ----------------
extern "C" void kernel_launch(void* const* d_in, const int* in_sizes, int n_in,
                              void* d_out, int out_size)
{
    (void)in_sizes; (void)n_in; (void)out_size;
    const float* x           = (const float*)d_in[0];
    const float* norm1_w     = (const float*)d_in[1];
    const float* tm_mix_v    = (const float*)d_in[3];
    const float* tm_mix_r    = (const float*)d_in[4];
    const float* tm_value_w  = (const float*)d_in[6];
    const float* tm_recept_w = (const float*)d_in[7];
    const float* tm_out_w    = (const float*)d_in[8];
    const float* sa_q_w      = (const float*)d_in[9];
    const float* sa_q_b      = (const float*)d_in[10];
    const float* sa_k_w      = (const float*)d_in[11];
    const float* sa_k_b      = (const float*)d_in[12];
    const float* sa_v_w      = (const float*)d_in[13];
    const float* sa_v_b      = (const float*)d_in[14];
    const float* sa_o_w      = (const float*)d_in[15];
    const float* sa_o_b      = (const float*)d_in[16];
    const float* norm2_w     = (const float*)d_in[17];
    const float* cm_mix_k    = (const float*)d_in[18];
    const float* cm_mix_r    = (const float*)d_in[19];
    const float* cm_key_w    = (const float*)d_in[20];
    const float* cm_recept_w = (const float*)d_in[21];
    const float* cm_value_w  = (const float*)d_in[22];
    float* out = (float*)d_out;

    float *x1, *bufV, *bufv, *bufr, *qb, *kb, *pv;
    int *pi;
    bf16 *x1h,*x1l,*mAh,*mAl,*mBh,*mBl,*aoh,*aol,*rkh,*rkl,*bgh,*bgl,*wH,*wL;
    cudaGetSymbolAddress((void**)&x1,   g_x1);
    cudaGetSymbolAddress((void**)&bufV, g_bufV);
    cudaGetSymbolAddress((void**)&bufv, g_bufv);
    cudaGetSymbolAddress((void**)&bufr, g_bufr);
    cudaGetSymbolAddress((void**)&qb,   g_q);
    cudaGetSymbolAddress((void**)&kb,   g_k);
    cudaGetSymbolAddress((void**)&pv,   g_pval);
    cudaGetSymbolAddress((void**)&pi,   g_pidx);
    cudaGetSymbolAddress((void**)&x1h,  g_x1h);
    cudaGetSymbolAddress((void**)&x1l,  g_x1l);
    cudaGetSymbolAddress((void**)&mAh,  g_mAh);
    cudaGetSymbolAddress((void**)&mAl,  g_mAl);
    cudaGetSymbolAddress((void**)&mBh,  g_mBh);
    cudaGetSymbolAddress((void**)&mBl,  g_mBl);
    cudaGetSymbolAddress((void**)&aoh,  g_aoh);
    cudaGetSymbolAddress((void**)&aol,  g_aol);
    cudaGetSymbolAddress((void**)&rkh,  g_rkh);
    cudaGetSymbolAddress((void**)&rkl,  g_rkl);
    cudaGetSymbolAddress((void**)&bgh,  g_bgh);
    cudaGetSymbolAddress((void**)&bgl,  g_bgl);
    cudaGetSymbolAddress((void**)&wH,   g_wH);
    cudaGetSymbolAddress((void**)&wL,   g_wL);

    cudaFuncSetAttribute(k_gemm<1,0>, cudaFuncAttributeMaxDynamicSharedMemorySize, GEMM_SMEM);
    cudaFuncSetAttribute(k_gemm<0,1>, cudaFuncAttributeMaxDynamicSharedMemorySize, GEMM_SMEM);
    cudaFuncSetAttribute(k_fat1,      cudaFuncAttributeMaxDynamicSharedMemorySize, GEMM_SMEM);
    cudaFuncSetAttribute(k_fat2,      cudaFuncAttributeMaxDynamicSharedMemorySize, GEMM_SMEM);

    const dim3 gD (D/128, NTOK/128);     // (8, 64)
    const dim3 gQK(1, NTOK/32, 2);

    // fat norm1: norm + tmv/tmr/sav weight splits
    Norm1Args n1;
    n1.x = x; n1.w = norm1_w; n1.mA = tm_mix_v; n1.mB = tm_mix_r;
    n1.oN = x1; n1.oNh = x1h; n1.oNl = x1l;
    n1.oAh = mAh; n1.oAl = mAl; n1.oBh = mBh; n1.oBl = mBl;
    n1.tmv_w = tm_value_w; n1.tmr_w = tm_recept_w; n1.sav_w = sa_v_w;
    n1.wH = wH; n1.wL = wL;
    k_norm1fat<<<NTOK + 3072, 256>>>(n1);

    qk_gemm<<<gQK, 256>>>(x1, sa_q_w, sa_q_b, qb, sa_k_w, sa_k_b, kb);

    // fat1: tmv + tmr + sav GEMMs + trailing weight splits (sao,tmo,cmr,cmk,cmv)
    Fat1Args f1;
    f1.mAh=mAh; f1.mAl=mAl; f1.mBh=mBh; f1.mBl=mBl; f1.x1h=x1h; f1.x1l=x1l;
    f1.wH=wH; f1.wL=wL; f1.bufv=bufv; f1.bufr=bufr; f1.bufV=bufV; f1.sa_v_b=sa_v_b;
    f1.sa_o_w=sa_o_w; f1.tm_out_w=tm_out_w; f1.cm_recept_w=cm_recept_w;
    f1.cm_key_w=cm_key_w; f1.cm_value_w=cm_value_w;
    k_fat1<<<12800, 256, GEMM_SMEM>>>(f1);

    topk_part<<<dim3(NTOK/64, KPART), 64>>>(qb, kb, pv, pi);
    topk_mg<<<NTOK, 256>>>(pv, pi, bufV, aoh, aol);

    k_gemm<0,1><<<gD, 256, GEMM_SMEM>>>(3, aoh, aol, wH+O_SAO, wL+O_SAO,
                                        nullptr, rkh, rkl, D, D, sa_o_b, bufr, bufv);  // rkv
    k_gemm<1,0><<<gD, 256, GEMM_SMEM>>>(4, rkh, rkl, wH+O_TMO, wL+O_TMO,
                                        out, nullptr, nullptr, D, D, nullptr, x, nullptr); // x2

    norm_mix_kernel<<<NTOK, 256>>>(out, norm2_w, cm_mix_k, cm_mix_r,
                                   nullptr, nullptr, nullptr, mAh, mAl, mBh, mBl);

    Fat2Args f2;
    f2.mAh=mAh; f2.mAl=mAl; f2.mBh=mBh; f2.mBl=mBl;
    f2.wH=wH; f2.wL=wL; f2.bgh=bgh; f2.bgl=bgl; f2.bufV=bufV;
    k_fat2<<<2560, 256, GEMM_SMEM>>>(f2);

    k_gemm<1,0><<<gD, 256, GEMM_SMEM>>>(5, bgh, bgl, wH+O_CMV, wL+O_CMV,
                                        out, nullptr, nullptr, DI, D, nullptr, out, bufV); // final
}